// round 16
// baseline (speedup 1.0000x reference)
#include <cuda_runtime.h>
#include <cuda_fp16.h>
#include <math.h>
#include <cstdint>

// Problem constants
#define HID 1024
#define NH  16
#define HD  64
#define BB  4
#define TT  2048
#define RR  8
#define SCALING 2.0f
#define L2E 1.4426950408889634f

// Scratch (device globals; no allocation allowed)
__device__ __half g_Weff[3 * HID * HID];        // fp16 folded weights [3072][1024]
__device__ __half g_Xh[BB * TT * HID];          // fp16 X
// Q,K: [mat][b][h][t][d] fp16 (Q pre-scaled by 1/8).  V: [b][h][d][t] fp16 (transposed).
__device__ __half g_QKVh[3 * BB * NH * TT * HD];

// ---------------------------------------------------------------------------
// helpers
// ---------------------------------------------------------------------------
__device__ __forceinline__ uint32_t smem_u32(const void* p) {
    uint32_t a;
    asm("{ .reg .u64 t; cvta.to.shared.u64 t, %1; cvt.u32.u64 %0, t; }" : "=r"(a) : "l"(p));
    return a;
}
__device__ __forceinline__ void mma_f16(float c[4], uint32_t a0, uint32_t a1, uint32_t a2, uint32_t a3,
                                        uint32_t b0, uint32_t b1) {
    asm volatile(
        "mma.sync.aligned.m16n8k16.row.col.f32.f16.f16.f32 "
        "{%0,%1,%2,%3},{%4,%5,%6,%7},{%8,%9},{%0,%1,%2,%3};"
        : "+f"(c[0]), "+f"(c[1]), "+f"(c[2]), "+f"(c[3])
        : "r"(a0), "r"(a1), "r"(a2), "r"(a3), "r"(b0), "r"(b1));
}
__device__ __forceinline__ void ldm_x4(uint32_t& f0, uint32_t& f1, uint32_t& f2, uint32_t& f3, uint32_t addr) {
    asm volatile("ldmatrix.sync.aligned.m8n8.x4.shared.b16 {%0,%1,%2,%3}, [%4];"
                 : "=r"(f0), "=r"(f1), "=r"(f2), "=r"(f3) : "r"(addr));
}
__device__ __forceinline__ uint32_t ex2_h2(uint32_t x) {
    uint32_t r; asm volatile("ex2.approx.f16x2 %0, %1;" : "=r"(r) : "r"(x)); return r;
}
__device__ __forceinline__ uint32_t pack_h2(float a, float b) {
    __half2 h = __floats2half2_rn(a, b);
    return *(uint32_t*)&h;
}
__device__ __forceinline__ void cp_async16(uint32_t smem, const void* gmem) {
    asm volatile("cp.async.cg.shared.global [%0], [%1], 16;" :: "r"(smem), "l"(gmem));
}
#define CP_COMMIT() asm volatile("cp.async.commit_group;" ::: "memory")
template <int N> __device__ __forceinline__ void cp_wait() {
    asm volatile("cp.async.wait_group %0;" :: "n"(N) : "memory");
}

// ---------------------------------------------------------------------------
// Kernel 1: fold LoRA (fp16, float4-vectorized) + convert X (fp16), one launch.
// ---------------------------------------------------------------------------
#define FOLD_BLOCKS 3072
#define PREP_BLOCKS (FOLD_BLOCKS + 8192)
__global__ void prep_kernel(const float* __restrict__ X,
                            const float* __restrict__ W0, const float* __restrict__ A0, const float* __restrict__ B0,
                            const float* __restrict__ W1, const float* __restrict__ A1, const float* __restrict__ B1,
                            const float* __restrict__ W2, const float* __restrict__ A2, const float* __restrict__ B2) {
    if (blockIdx.x < FOLD_BLOCKS) {
        int idx4 = blockIdx.x * blockDim.x + threadIdx.x;   // float4 index into [3][1024][256]
        int mat  = idx4 >> 18;
        int rem  = idx4 & ((1 << 18) - 1);
        int o    = rem >> 8;
        int i4   = rem & 255;
        const float* W = (mat == 0) ? W0 : (mat == 1) ? W1 : W2;
        const float* A = (mat == 0) ? A0 : (mat == 1) ? A1 : A2;
        const float* Bm = (mat == 0) ? B0 : (mat == 1) ? B1 : B2;
        float4 acc = ((const float4*)W)[(size_t)o * 256 + i4];
#pragma unroll
        for (int r = 0; r < RR; r++) {
            float s = SCALING * Bm[o * RR + r];
            float4 a = ((const float4*)A)[(size_t)r * 256 + i4];
            acc.x += s * a.x; acc.y += s * a.y; acc.z += s * a.z; acc.w += s * a.w;
        }
        uint2 oh;
        oh.x = pack_h2(acc.x, acc.y);
        oh.y = pack_h2(acc.z, acc.w);
        ((uint2*)g_Weff)[idx4] = oh;
    } else {
        int i = (blockIdx.x - FOLD_BLOCKS) * blockDim.x + threadIdx.x;  // float4 idx
        float4 v = ((const float4*)X)[i];
        uint2 o;
        o.x = pack_h2(v.x, v.y);
        o.y = pack_h2(v.z, v.w);
        ((uint2*)g_Xh)[i] = o;
    }
}

// ---------------------------------------------------------------------------
// Kernel 2: QKV GEMM. BM=BN=128, BK=64, 3-stage cp.async — unchanged from R11.
// ---------------------------------------------------------------------------
#define GSTAGES 3
#define GSTR 72                                   // halves per row (144B)
#define GTILE_B (128 * GSTR * 2)                  // 18432
#define STG_BYTES (2 * GTILE_B)                   // 36864
#define GEMM_SMEM (GSTAGES * STG_BYTES)           // 110592

__global__ void __launch_bounds__(256, 2)
qkv_gemm_mma(const float* __restrict__ bq, const float* __restrict__ bk, const float* __restrict__ bv) {
    extern __shared__ __half smh[];
    uint32_t sbase = smem_u32(smh);

    int tid = threadIdx.x;
    int w    = tid >> 5;
    int lane = tid & 31;
    int gid  = lane >> 2;
    int tid4 = lane & 3;
    int wm = w & 1;
    int wn = w >> 1;
    int j = lane >> 3, r = lane & 7;
    uint32_t offA = (uint32_t)(((j & 1) * 8 + r) * GSTR + (j >> 1) * 8) * 2;
    uint32_t offB = (uint32_t)(((j >> 1) * 8 + r) * GSTR + (j & 1) * 8) * 2;

    int m0b = blockIdx.y * 128;
    int n0b = blockIdx.x * 128;
    const __half* Wp = g_Weff;
    const __half* Xp = g_Xh;

    auto load_stage = [&](int kt, int slot) {
        int k0 = kt * 64;
        uint32_t sa = sbase + (uint32_t)slot * STG_BYTES;
        uint32_t sb = sa + GTILE_B;
#pragma unroll
        for (int i = 0; i < 4; i++) {
            int ch = tid + i * 256;                // 0..1023
            int row = ch >> 3, c8 = ch & 7;
            uint32_t off = (uint32_t)(row * 144 + c8 * 16);
            cp_async16(sa + off, Xp + (size_t)(m0b + row) * HID + k0 + c8 * 8);
            cp_async16(sb + off, Wp + (size_t)(n0b + row) * HID + k0 + c8 * 8);
        }
        CP_COMMIT();
    };

    float acc[4][4][4];
#pragma unroll
    for (int mm = 0; mm < 4; mm++)
#pragma unroll
        for (int nn = 0; nn < 4; nn++)
#pragma unroll
            for (int jj = 0; jj < 4; jj++) acc[mm][nn][jj] = 0.f;

    load_stage(0, 0);
    load_stage(1, 1);

    const int NKT = HID / 64;   // 16
    for (int kt = 0; kt < NKT; kt++) {
        int slot = kt % GSTAGES;
        if (kt >= NKT - 2) cp_wait<0>(); else cp_wait<1>();
        __syncthreads();
        if (kt + 2 < NKT) load_stage(kt + 2, (kt + 2) % GSTAGES);

        uint32_t aB = sbase + slot * STG_BYTES + (uint32_t)(wm * 64) * GSTR * 2 + offA;
        uint32_t bB = sbase + slot * STG_BYTES + GTILE_B + (uint32_t)(wn * 32) * GSTR * 2 + offB;
#pragma unroll
        for (int ks = 0; ks < 4; ks++) {
            uint32_t af[4][4];
#pragma unroll
            for (int mm = 0; mm < 4; mm++)
                ldm_x4(af[mm][0], af[mm][1], af[mm][2], af[mm][3],
                       aB + (uint32_t)(mm * 16 * GSTR + ks * 16) * 2);
            uint32_t bf[4][2];
#pragma unroll
            for (int p = 0; p < 2; p++)
                ldm_x4(bf[2 * p][0], bf[2 * p][1], bf[2 * p + 1][0], bf[2 * p + 1][1],
                       bB + (uint32_t)(p * 16 * GSTR + ks * 16) * 2);
#pragma unroll
            for (int mm = 0; mm < 4; mm++)
#pragma unroll
                for (int nn = 0; nn < 4; nn++)
                    mma_f16(acc[mm][nn], af[mm][0], af[mm][1], af[mm][2], af[mm][3], bf[nn][0], bf[nn][1]);
        }
    }

    // epilogue
#pragma unroll
    for (int nn = 0; nn < 4; nn++) {
        int c = n0b + wn * 32 + nn * 8 + tid4 * 2;
        int mat = c >> 10;
        int o = c & 1023;
        const float* bias = (mat == 0) ? bq : (mat == 1) ? bk : bv;
        float b0v = bias[o], b1v = bias[o + 1];
        float scl = (mat == 0) ? 0.125f : 1.0f;
        int h = o >> 6, d = o & 63;
#pragma unroll
        for (int mm = 0; mm < 4; mm++) {
#pragma unroll
            for (int half_ : {0, 1}) {
                int m = m0b + wm * 64 + mm * 16 + gid + half_ * 8;
                int bi = m >> 11, t = m & 2047;
                float v0 = (acc[mm][nn][2 * half_ + 0] + b0v) * scl;
                float v1 = (acc[mm][nn][2 * half_ + 1] + b1v) * scl;
                if (mat == 2) {
                    __half* vb = g_QKVh + ((size_t)((2 * BB + bi) * NH + h)) * (TT * HD);
                    vb[(size_t)d * TT + t]       = __float2half_rn(v0);
                    vb[(size_t)(d + 1) * TT + t] = __float2half_rn(v1);
                } else {
                    __half* dst = g_QKVh + ((size_t)((mat * BB + bi) * NH + h) * TT + t) * HD + d;
                    *(uint32_t*)dst = pack_h2(v0, v1);
                }
            }
        }
    }
}

// ---------------------------------------------------------------------------
// Kernel 3: causal flash attention — max-free softmax (R15) + PAIRED k-tiles:
// one sync per 128 cols; schedule S(A) -> PV(prevB) -> exp(A) -> S(B) ->
// PV(A) -> exp(B) keeps cS/ph live-ranges identical to R15 (no R10 blowout).
// Diagonal: warps 0-3 skip tile B entirely (exact). NSTG=5 ring (92KB, 2 CTA/SM).
// ---------------------------------------------------------------------------
#define QR 128
#define KTL 64
#define STK 72
#define NSTG 5
#define KSTGB (KTL * STK * 2)                    // 9216
#define OFF_K 0
#define OFF_V (NSTG * KSTGB)
#define ATTN_SMEM (2 * NSTG * KSTGB)             // 92160

__global__ void __launch_bounds__(256, 2)
attn_mma(const float* __restrict__ mask, float* __restrict__ out) {
    extern __shared__ __half smh[];
    uint32_t sb = smem_u32(smh);

    int qt = gridDim.x - 1 - blockIdx.x;   // heavy blocks first
    int h  = blockIdx.y;
    int b  = blockIdx.z;

    const __half* Qg  = g_QKVh + (size_t)((0 * BB + b) * NH + h) * TT * HD;
    const __half* Kg  = g_QKVh + (size_t)((1 * BB + b) * NH + h) * TT * HD;
    const __half* Vtg = g_QKVh + (size_t)((2 * BB + b) * NH + h) * (TT * HD); // [d][t]
    const float* maskb = mask + (size_t)b * TT;

    int tid = threadIdx.x;
    int w    = tid >> 5;
    int lane = tid & 31;
    int gid  = lane >> 2;
    int tid4 = lane & 3;
    int rowb = w * 16;
    int j = lane >> 3, r = lane & 7;
    uint32_t lmoff = (uint32_t)(((j >> 1) * 8 + r) * STK + (j & 1) * 8) * 2;  // bytes

    const int niter = qt + 1;              // pairs of 64-wide k-tiles
    const int q0 = qt * QR + rowb + gid;
    const int q1 = q0 + 8;

    auto loadKV = [&](int t_) {
        int s = t_ % NSTG;
#pragma unroll
        for (int i = 0; i < 2; i++) {
            int ch = tid + i * 256;
            int rr = ch >> 3, c = ch & 7;
            cp_async16(sb + OFF_K + s * KSTGB + rr * 144 + c * 16,
                       Kg + (size_t)(t_ * KTL + rr) * HD + c * 8);
        }
#pragma unroll
        for (int i = 0; i < 2; i++) {
            int ch = tid + i * 256;
            int rr = ch >> 3, c = ch & 7;
            cp_async16(sb + OFF_V + s * KSTGB + rr * 144 + c * 16,
                       Vtg + (size_t)rr * TT + t_ * KTL + c * 8);
        }
    };
    auto loadPair = [&](int it_) {
        loadKV(2 * it_);
        loadKV(2 * it_ + 1);
        CP_COMMIT();
    };

    // Q fragments in registers (Q pre-scaled by 1/8)
    uint32_t qf[4][4];
#pragma unroll
    for (int ks = 0; ks < 4; ks++) {
        int kc = ks * 16;
        qf[ks][0] = *(const uint32_t*)&Qg[(size_t)q0 * HD + kc + 2 * tid4];
        qf[ks][1] = *(const uint32_t*)&Qg[(size_t)q1 * HD + kc + 2 * tid4];
        qf[ks][2] = *(const uint32_t*)&Qg[(size_t)q0 * HD + kc + 8 + 2 * tid4];
        qf[ks][3] = *(const uint32_t*)&Qg[(size_t)q1 * HD + kc + 8 + 2 * tid4];
    }

    loadPair(0);

    float cO[8][4];
#pragma unroll
    for (int nn = 0; nn < 8; nn++)
#pragma unroll
        for (int jj = 0; jj < 4; jj++) cO[nn][jj] = 0.f;
    float cL[4] = {0.f, 0.f, 0.f, 0.f};   // persistent l accumulator (ones-MMA)
    float cS[8][4];
    uint32_t ph[8][2];
    const uint32_t ones_b = (gid == 0) ? 0x3C003C00u : 0u;

    auto s_mma = [&](int t_) {
        uint32_t kB = sb + OFF_K + (uint32_t)((t_ % NSTG) * KSTGB) + lmoff;
#pragma unroll
        for (int nn = 0; nn < 8; nn++)
#pragma unroll
            for (int jj = 0; jj < 4; jj++) cS[nn][jj] = 0.f;
#pragma unroll
        for (int ks = 0; ks < 4; ks++) {
#pragma unroll
            for (int p = 0; p < 4; p++) {
                uint32_t f0, f1, f2, f3;
                ldm_x4(f0, f1, f2, f3, kB + (uint32_t)(p * 16 * STK + ks * 16) * 2);
                mma_f16(cS[2 * p],     qf[ks][0], qf[ks][1], qf[ks][2], qf[ks][3], f0, f1);
                mma_f16(cS[2 * p + 1], qf[ks][0], qf[ks][1], qf[ks][2], qf[ks][3], f2, f3);
            }
        }
    };
    auto exp_tile = [&](int t_, bool dodiag) {
        int colb0 = t_ * KTL;
#pragma unroll
        for (int nn = 0; nn < 8; nn++) {
            int c = colb0 + nn * 8 + 2 * tid4;
            float mk0 = __ldg(&maskb[c]);
            float mk1 = __ldg(&maskb[c + 1]);
            float f0 = (cS[nn][0] + mk0) * L2E;
            float f1 = (cS[nn][1] + mk1) * L2E;
            float f2 = (cS[nn][2] + mk0) * L2E;
            float f3 = (cS[nn][3] + mk1) * L2E;
            if (dodiag) {
                if (c     > q0) f0 = -6.0e4f;
                if (c + 1 > q0) f1 = -6.0e4f;
                if (c     > q1) f2 = -6.0e4f;
                if (c + 1 > q1) f3 = -6.0e4f;
            }
            ph[nn][0] = ex2_h2(pack_h2(f0, f1));
            ph[nn][1] = ex2_h2(pack_h2(f2, f3));
        }
    };
    auto pv_block = [&](int t_) {
        uint32_t vB = sb + OFF_V + (uint32_t)((t_ % NSTG) * KSTGB) + lmoff;
#pragma unroll
        for (int ks = 0; ks < 4; ks++)
            mma_f16(cL, ph[2 * ks][0], ph[2 * ks][1], ph[2 * ks + 1][0], ph[2 * ks + 1][1],
                    ones_b, ones_b);
#pragma unroll
        for (int ks = 0; ks < 4; ks++) {
#pragma unroll
            for (int p = 0; p < 4; p++) {
                uint32_t f0, f1, f2, f3;
                ldm_x4(f0, f1, f2, f3, vB + (uint32_t)(p * 16 * STK + ks * 16) * 2);
                mma_f16(cO[2 * p],     ph[2 * ks][0], ph[2 * ks][1], ph[2 * ks + 1][0], ph[2 * ks + 1][1], f0, f1);
                mma_f16(cO[2 * p + 1], ph[2 * ks][0], ph[2 * ks][1], ph[2 * ks + 1][0], ph[2 * ks + 1][1], f2, f3);
            }
        }
    };

    for (int it = 0; it < niter; it++) {
        cp_wait<0>();
        __syncthreads();
        if (it + 1 < niter) loadPair(it + 1);

        int tA = 2 * it;
        bool isdiag = (it == qt);
        bool activeB = !isdiag || (w >= 4);

        s_mma(tA);                               // cS <- A
        if (it > 0) pv_block(tA - 1);            // PV(prev B), overlaps S(A)
        exp_tile(tA, isdiag && (w < 4));         // ph <- A (cS free)
        if (activeB) s_mma(tA + 1);              // cS <- B
        pv_block(tA);                            // PV(A), overlaps S(B)
        if (activeB) exp_tile(tA + 1, isdiag);   // ph <- B
    }
    // drain: last pair's tile B (active only for warps 4-7 on the diagonal)
    if (w >= 4) pv_block(2 * qt + 1);

    // l lives in cL[0]/cL[2] on tid4==0 lanes; broadcast within quad
    float l0 = __shfl_sync(0xffffffffu, cL[0], lane & ~3);
    float l1 = __shfl_sync(0xffffffffu, cL[2], lane & ~3);
    float inv0 = 1.f / l0;
    float inv1 = 1.f / l1;
#pragma unroll
    for (int nn = 0; nn < 8; nn++) {
        int d = nn * 8 + tid4 * 2;
        float* o0p = out + ((size_t)(b * TT + q0)) * (NH * HD) + h * HD + d;
        *(float2*)o0p = make_float2(cO[nn][0] * inv0, cO[nn][1] * inv0);
        float* o1p = out + ((size_t)(b * TT + q1)) * (NH * HD) + h * HD + d;
        *(float2*)o1p = make_float2(cO[nn][2] * inv1, cO[nn][3] * inv1);
    }
}

// ---------------------------------------------------------------------------
extern "C" void kernel_launch(void* const* d_in, const int* in_sizes, int n_in,
                              void* d_out, int out_size) {
    const float* X    = (const float*)d_in[0];
    const float* mask = (const float*)d_in[1];
    const float* Wq = (const float*)d_in[2];
    const float* bq = (const float*)d_in[3];
    const float* Aq = (const float*)d_in[4];
    const float* Bq = (const float*)d_in[5];
    const float* Wk = (const float*)d_in[6];
    const float* bk = (const float*)d_in[7];
    const float* Ak = (const float*)d_in[8];
    const float* Bk = (const float*)d_in[9];
    const float* Wv = (const float*)d_in[10];
    const float* bv = (const float*)d_in[11];
    const float* Av = (const float*)d_in[12];
    const float* Bv = (const float*)d_in[13];
    float* out = (float*)d_out;

    // 1) fold LoRA (vectorized) + convert X (single launch)
    prep_kernel<<<PREP_BLOCKS, 256>>>(X, Wq, Aq, Bq, Wk, Ak, Bk, Wv, Av, Bv);

    // 2) fused QKV projection (fp16 mma, BK=64, 3-stage)
    cudaFuncSetAttribute(qkv_gemm_mma, cudaFuncAttributeMaxDynamicSharedMemorySize, GEMM_SMEM);
    qkv_gemm_mma<<<dim3(3 * HID / 128, BB * TT / 128), 256, GEMM_SMEM>>>(bq, bk, bv);

    // 3) causal flash attention (max-free softmax, paired k-tiles)
    cudaFuncSetAttribute(attn_mma, cudaFuncAttributeMaxDynamicSharedMemorySize, ATTN_SMEM);
    attn_mma<<<dim3(TT / QR, NH, BB), 256, ATTN_SMEM>>>(mask, out);
    (void)in_sizes; (void)n_in; (void)out_size;
}

// round 17
// speedup vs baseline: 1.0383x; 1.0383x over previous
#include <cuda_runtime.h>
#include <cuda_fp16.h>
#include <math.h>
#include <cstdint>

// Problem constants
#define HID 1024
#define NH  16
#define HD  64
#define BB  4
#define TT  2048
#define RR  8
#define SCALING 2.0f
#define L2E 1.4426950408889634f

// Scratch (device globals; no allocation allowed)
__device__ __half g_Weff[3 * HID * HID];        // fp16 folded weights [3072][1024]
__device__ __half g_Xh[BB * TT * HID];          // fp16 X
// Q,K: [mat][b][h][t][d] fp16 (Q pre-scaled by 1/8).  V: [b][h][d][t] fp16 (transposed).
__device__ __half g_QKVh[3 * BB * NH * TT * HD];

// ---------------------------------------------------------------------------
// helpers
// ---------------------------------------------------------------------------
__device__ __forceinline__ uint32_t smem_u32(const void* p) {
    uint32_t a;
    asm("{ .reg .u64 t; cvta.to.shared.u64 t, %1; cvt.u32.u64 %0, t; }" : "=r"(a) : "l"(p));
    return a;
}
__device__ __forceinline__ void mma_f16(float c[4], uint32_t a0, uint32_t a1, uint32_t a2, uint32_t a3,
                                        uint32_t b0, uint32_t b1) {
    asm volatile(
        "mma.sync.aligned.m16n8k16.row.col.f32.f16.f16.f32 "
        "{%0,%1,%2,%3},{%4,%5,%6,%7},{%8,%9},{%0,%1,%2,%3};"
        : "+f"(c[0]), "+f"(c[1]), "+f"(c[2]), "+f"(c[3])
        : "r"(a0), "r"(a1), "r"(a2), "r"(a3), "r"(b0), "r"(b1));
}
__device__ __forceinline__ void ldm_x4(uint32_t& f0, uint32_t& f1, uint32_t& f2, uint32_t& f3, uint32_t addr) {
    asm volatile("ldmatrix.sync.aligned.m8n8.x4.shared.b16 {%0,%1,%2,%3}, [%4];"
                 : "=r"(f0), "=r"(f1), "=r"(f2), "=r"(f3) : "r"(addr));
}
__device__ __forceinline__ uint32_t ex2_h2(uint32_t x) {
    uint32_t r; asm volatile("ex2.approx.f16x2 %0, %1;" : "=r"(r) : "r"(x)); return r;
}
__device__ __forceinline__ uint32_t pack_h2(float a, float b) {
    __half2 h = __floats2half2_rn(a, b);
    return *(uint32_t*)&h;
}
__device__ __forceinline__ void cp_async16(uint32_t smem, const void* gmem) {
    asm volatile("cp.async.cg.shared.global [%0], [%1], 16;" :: "r"(smem), "l"(gmem));
}
#define CP_COMMIT() asm volatile("cp.async.commit_group;" ::: "memory")
template <int N> __device__ __forceinline__ void cp_wait() {
    asm volatile("cp.async.wait_group %0;" :: "n"(N) : "memory");
}

// ---------------------------------------------------------------------------
// Kernel 1: fold LoRA (fp16, float4-vectorized) + convert X (fp16), one launch.
// ---------------------------------------------------------------------------
#define FOLD_BLOCKS 3072
#define PREP_BLOCKS (FOLD_BLOCKS + 8192)
__global__ void prep_kernel(const float* __restrict__ X,
                            const float* __restrict__ W0, const float* __restrict__ A0, const float* __restrict__ B0,
                            const float* __restrict__ W1, const float* __restrict__ A1, const float* __restrict__ B1,
                            const float* __restrict__ W2, const float* __restrict__ A2, const float* __restrict__ B2) {
    if (blockIdx.x < FOLD_BLOCKS) {
        int idx4 = blockIdx.x * blockDim.x + threadIdx.x;   // float4 index into [3][1024][256]
        int mat  = idx4 >> 18;
        int rem  = idx4 & ((1 << 18) - 1);
        int o    = rem >> 8;
        int i4   = rem & 255;
        const float* W = (mat == 0) ? W0 : (mat == 1) ? W1 : W2;
        const float* A = (mat == 0) ? A0 : (mat == 1) ? A1 : A2;
        const float* Bm = (mat == 0) ? B0 : (mat == 1) ? B1 : B2;
        float4 acc = ((const float4*)W)[(size_t)o * 256 + i4];
#pragma unroll
        for (int r = 0; r < RR; r++) {
            float s = SCALING * Bm[o * RR + r];
            float4 a = ((const float4*)A)[(size_t)r * 256 + i4];
            acc.x += s * a.x; acc.y += s * a.y; acc.z += s * a.z; acc.w += s * a.w;
        }
        uint2 oh;
        oh.x = pack_h2(acc.x, acc.y);
        oh.y = pack_h2(acc.z, acc.w);
        ((uint2*)g_Weff)[idx4] = oh;
    } else {
        int i = (blockIdx.x - FOLD_BLOCKS) * blockDim.x + threadIdx.x;  // float4 idx
        float4 v = ((const float4*)X)[i];
        uint2 o;
        o.x = pack_h2(v.x, v.y);
        o.y = pack_h2(v.z, v.w);
        ((uint2*)g_Xh)[i] = o;
    }
}

// ---------------------------------------------------------------------------
// Kernel 2: QKV GEMM. BM=BN=128, BK=64, 3-stage cp.async.
// Epilogue stages the 128x128 output tile through smem for coalesced stores
// (Q/K: per-t rows; V: transposed per-d rows).
// ---------------------------------------------------------------------------
#define GSTAGES 3
#define GSTR 72                                   // halves per row (144B)
#define GTILE_B (128 * GSTR * 2)                  // 18432
#define STG_BYTES (2 * GTILE_B)                   // 36864
#define GEMM_SMEM (GSTAGES * STG_BYTES)           // 110592
#define OST 136                                   // epilogue smem stride (halves)

__global__ void __launch_bounds__(256, 2)
qkv_gemm_mma(const float* __restrict__ bq, const float* __restrict__ bk, const float* __restrict__ bv) {
    extern __shared__ __half smh[];
    uint32_t sbase = smem_u32(smh);

    int tid = threadIdx.x;
    int w    = tid >> 5;
    int lane = tid & 31;
    int gid  = lane >> 2;
    int tid4 = lane & 3;
    int wm = w & 1;
    int wn = w >> 1;
    int j = lane >> 3, r = lane & 7;
    uint32_t offA = (uint32_t)(((j & 1) * 8 + r) * GSTR + (j >> 1) * 8) * 2;
    uint32_t offB = (uint32_t)(((j >> 1) * 8 + r) * GSTR + (j & 1) * 8) * 2;

    int m0b = blockIdx.y * 128;
    int n0b = blockIdx.x * 128;
    const __half* Wp = g_Weff;
    const __half* Xp = g_Xh;

    auto load_stage = [&](int kt, int slot) {
        int k0 = kt * 64;
        uint32_t sa = sbase + (uint32_t)slot * STG_BYTES;
        uint32_t sb = sa + GTILE_B;
#pragma unroll
        for (int i = 0; i < 4; i++) {
            int ch = tid + i * 256;                // 0..1023
            int row = ch >> 3, c8 = ch & 7;
            uint32_t off = (uint32_t)(row * 144 + c8 * 16);
            cp_async16(sa + off, Xp + (size_t)(m0b + row) * HID + k0 + c8 * 8);
            cp_async16(sb + off, Wp + (size_t)(n0b + row) * HID + k0 + c8 * 8);
        }
        CP_COMMIT();
    };

    float acc[4][4][4];
#pragma unroll
    for (int mm = 0; mm < 4; mm++)
#pragma unroll
        for (int nn = 0; nn < 4; nn++)
#pragma unroll
            for (int jj = 0; jj < 4; jj++) acc[mm][nn][jj] = 0.f;

    load_stage(0, 0);
    load_stage(1, 1);

    const int NKT = HID / 64;   // 16
    for (int kt = 0; kt < NKT; kt++) {
        int slot = kt % GSTAGES;
        if (kt >= NKT - 2) cp_wait<0>(); else cp_wait<1>();
        __syncthreads();
        if (kt + 2 < NKT) load_stage(kt + 2, (kt + 2) % GSTAGES);

        uint32_t aB = sbase + slot * STG_BYTES + (uint32_t)(wm * 64) * GSTR * 2 + offA;
        uint32_t bB = sbase + slot * STG_BYTES + GTILE_B + (uint32_t)(wn * 32) * GSTR * 2 + offB;
#pragma unroll
        for (int ks = 0; ks < 4; ks++) {
            uint32_t af[4][4];
#pragma unroll
            for (int mm = 0; mm < 4; mm++)
                ldm_x4(af[mm][0], af[mm][1], af[mm][2], af[mm][3],
                       aB + (uint32_t)(mm * 16 * GSTR + ks * 16) * 2);
            uint32_t bf[4][2];
#pragma unroll
            for (int p = 0; p < 2; p++)
                ldm_x4(bf[2 * p][0], bf[2 * p][1], bf[2 * p + 1][0], bf[2 * p + 1][1],
                       bB + (uint32_t)(p * 16 * GSTR + ks * 16) * 2);
#pragma unroll
            for (int mm = 0; mm < 4; mm++)
#pragma unroll
                for (int nn = 0; nn < 4; nn++)
                    mma_f16(acc[mm][nn], af[mm][0], af[mm][1], af[mm][2], af[mm][3], bf[nn][0], bf[nn][1]);
        }
    }

    // ---- epilogue: bias/scale, stage tile in smem, coalesced stores ----
    __syncthreads();                               // mainloop smem reads done
    __half* Osm = smh;                             // 128*OST halves = 34816 B
    int mat = n0b >> 10;                           // uniform per CTA
    float scl = (mat == 0) ? 0.125f : 1.0f;
    int bi = m0b >> 11, t0 = m0b & 2047;
    int h0 = (n0b & 1023) >> 6;

    if (mat == 2) {
        // V: stage transposed [cl][lm]
#pragma unroll
        for (int nn = 0; nn < 4; nn++) {
            int cl = wn * 32 + nn * 8 + tid4 * 2;
            int o = (n0b & 1023) + cl;
            float b0v = bv[o], b1v = bv[o + 1];
#pragma unroll
            for (int mm = 0; mm < 4; mm++) {
#pragma unroll
                for (int half_ = 0; half_ < 2; half_++) {
                    int lm = wm * 64 + mm * 16 + gid + half_ * 8;
                    Osm[cl * OST + lm]       = __float2half_rn(acc[mm][nn][2 * half_ + 0] + b0v);
                    Osm[(cl + 1) * OST + lm] = __float2half_rn(acc[mm][nn][2 * half_ + 1] + b1v);
                }
            }
        }
        __syncthreads();
#pragma unroll
        for (int i = 0; i < 8; i++) {
            int idx = tid + i * 256;               // 0..2047
            int row = idx >> 4, c16 = idx & 15;    // row = cl (d-col), 16 uint4/row
            uint4 v = *(uint4*)&Osm[row * OST + c16 * 8];
            int hh = h0 + (row >> 6), d = row & 63;
            __half* dst = g_QKVh + ((size_t)((2 * BB + bi) * NH + hh)) * (TT * HD)
                          + (size_t)d * TT + t0 + c16 * 8;
            *(uint4*)dst = v;
        }
    } else {
        const float* bias = (mat == 0) ? bq : bk;
        // Q/K: stage [lm][cl]
#pragma unroll
        for (int nn = 0; nn < 4; nn++) {
            int cl = wn * 32 + nn * 8 + tid4 * 2;
            int o = (n0b & 1023) + cl;
            float b0v = bias[o], b1v = bias[o + 1];
#pragma unroll
            for (int mm = 0; mm < 4; mm++) {
#pragma unroll
                for (int half_ = 0; half_ < 2; half_++) {
                    int lm = wm * 64 + mm * 16 + gid + half_ * 8;
                    *(uint32_t*)&Osm[lm * OST + cl] =
                        pack_h2((acc[mm][nn][2 * half_ + 0] + b0v) * scl,
                                (acc[mm][nn][2 * half_ + 1] + b1v) * scl);
                }
            }
        }
        __syncthreads();
#pragma unroll
        for (int i = 0; i < 8; i++) {
            int idx = tid + i * 256;
            int row = idx >> 4, c16 = idx & 15;    // row = lm (t-row)
            uint4 v = *(uint4*)&Osm[row * OST + c16 * 8];
            int hh = h0 + (c16 >> 3);
            int dd = (c16 & 7) * 8;
            __half* dst = g_QKVh + ((size_t)((mat * BB + bi) * NH + hh)) * (TT * HD)
                          + (size_t)(t0 + row) * HD + dd;
            *(uint4*)dst = v;
        }
    }
}

// ---------------------------------------------------------------------------
// Kernel 3: causal flash attention — R15 version verbatim (best measured).
// Max-free softmax, PV pipelined one tile behind, NSTG=4, 2 CTA/SM.
// ---------------------------------------------------------------------------
#define QR 128
#define KTL 64
#define STK 72
#define NSTG 4
#define KSTGB (KTL * STK * 2)                    // 9216
#define OFF_K 0
#define OFF_V (NSTG * KSTGB)
#define ATTN_SMEM (2 * NSTG * KSTGB)             // 73728

__global__ void __launch_bounds__(256, 2)
attn_mma(const float* __restrict__ mask, float* __restrict__ out) {
    extern __shared__ __half smh[];
    uint32_t sb = smem_u32(smh);

    int qt = gridDim.x - 1 - blockIdx.x;   // heavy blocks first
    int h  = blockIdx.y;
    int b  = blockIdx.z;

    const __half* Qg  = g_QKVh + (size_t)((0 * BB + b) * NH + h) * TT * HD;
    const __half* Kg  = g_QKVh + (size_t)((1 * BB + b) * NH + h) * TT * HD;
    const __half* Vtg = g_QKVh + (size_t)((2 * BB + b) * NH + h) * (TT * HD); // [d][t]
    const float* maskb = mask + (size_t)b * TT;

    int tid = threadIdx.x;
    int w    = tid >> 5;
    int lane = tid & 31;
    int gid  = lane >> 2;
    int tid4 = lane & 3;
    int rowb = w * 16;
    int j = lane >> 3, r = lane & 7;
    uint32_t lmoff = (uint32_t)(((j >> 1) * 8 + r) * STK + (j & 1) * 8) * 2;  // bytes

    int nkt = 2 * (qt + 1);
    const int q0 = qt * QR + rowb + gid;
    const int q1 = q0 + 8;

    auto loadKV = [&](int kt_) {
        int s = kt_ & (NSTG - 1);
#pragma unroll
        for (int i = 0; i < 2; i++) {
            int ch = tid + i * 256;
            int rr = ch >> 3, c = ch & 7;
            cp_async16(sb + OFF_K + s * KSTGB + rr * 144 + c * 16,
                       Kg + (size_t)(kt_ * KTL + rr) * HD + c * 8);
        }
#pragma unroll
        for (int i = 0; i < 2; i++) {
            int ch = tid + i * 256;
            int rr = ch >> 3, c = ch & 7;
            cp_async16(sb + OFF_V + s * KSTGB + rr * 144 + c * 16,
                       Vtg + (size_t)rr * TT + kt_ * KTL + c * 8);
        }
        CP_COMMIT();
    };

    // Q fragments in registers (Q pre-scaled by 1/8)
    uint32_t qf[4][4];
#pragma unroll
    for (int ks = 0; ks < 4; ks++) {
        int kc = ks * 16;
        qf[ks][0] = *(const uint32_t*)&Qg[(size_t)q0 * HD + kc + 2 * tid4];
        qf[ks][1] = *(const uint32_t*)&Qg[(size_t)q1 * HD + kc + 2 * tid4];
        qf[ks][2] = *(const uint32_t*)&Qg[(size_t)q0 * HD + kc + 8 + 2 * tid4];
        qf[ks][3] = *(const uint32_t*)&Qg[(size_t)q1 * HD + kc + 8 + 2 * tid4];
    }

    loadKV(0);
    if (nkt > 1) loadKV(1);

    float cO[8][4];
#pragma unroll
    for (int nn = 0; nn < 8; nn++)
#pragma unroll
        for (int jj = 0; jj < 4; jj++) cO[nn][jj] = 0.f;
    float cL[4] = {0.f, 0.f, 0.f, 0.f};   // persistent l accumulator (ones-MMA)
    uint32_t ph[8][2];
    const uint32_t ones_b = (gid == 0) ? 0x3C003C00u : 0u;

    auto pv_block = [&](int kt_) {
        uint32_t vB = sb + OFF_V + (kt_ & (NSTG - 1)) * KSTGB + lmoff;
#pragma unroll
        for (int ks = 0; ks < 4; ks++) {
#pragma unroll
            for (int p = 0; p < 4; p++) {
                uint32_t f0, f1, f2, f3;
                ldm_x4(f0, f1, f2, f3, vB + (uint32_t)(p * 16 * STK + ks * 16) * 2);
                mma_f16(cO[2 * p],     ph[2 * ks][0], ph[2 * ks][1], ph[2 * ks + 1][0], ph[2 * ks + 1][1], f0, f1);
                mma_f16(cO[2 * p + 1], ph[2 * ks][0], ph[2 * ks][1], ph[2 * ks + 1][0], ph[2 * ks + 1][1], f2, f3);
            }
        }
    };

    for (int kt = 0; kt < nkt; kt++) {
        if (kt + 1 < nkt) cp_wait<1>(); else cp_wait<0>();
        __syncthreads();
        if (kt + 2 < nkt) loadKV(kt + 2);

        uint32_t kB = sb + OFF_K + (kt & (NSTG - 1)) * KSTGB + lmoff;

        // ---- S = Q @ K^T (tile kt) ----
        float cS[8][4];
#pragma unroll
        for (int nn = 0; nn < 8; nn++)
#pragma unroll
            for (int jj = 0; jj < 4; jj++) cS[nn][jj] = 0.f;
#pragma unroll
        for (int ks = 0; ks < 4; ks++) {
#pragma unroll
            for (int p = 0; p < 4; p++) {
                uint32_t f0, f1, f2, f3;
                ldm_x4(f0, f1, f2, f3, kB + (uint32_t)(p * 16 * STK + ks * 16) * 2);
                mma_f16(cS[2 * p],     qf[ks][0], qf[ks][1], qf[ks][2], qf[ks][3], f0, f1);
                mma_f16(cS[2 * p + 1], qf[ks][0], qf[ks][1], qf[ks][2], qf[ks][3], f2, f3);
            }
        }

        // ---- PV of PREVIOUS tile (overlaps S-MMA latency) ----
        if (kt > 0) pv_block(kt - 1);

        // ---- mask + causal + direct exp (no max subtraction) ----
        int colb0 = kt * KTL;
        bool diag = (kt >= 2 * qt);
#pragma unroll
        for (int nn = 0; nn < 8; nn++) {
            int c = colb0 + nn * 8 + 2 * tid4;
            float mk0 = __ldg(&maskb[c]);
            float mk1 = __ldg(&maskb[c + 1]);
            float f0 = fmaf(cS[nn][0] + mk0, L2E, 0.f);
            float f1 = fmaf(cS[nn][1] + mk1, L2E, 0.f);
            float f2 = fmaf(cS[nn][2] + mk0, L2E, 0.f);
            float f3 = fmaf(cS[nn][3] + mk1, L2E, 0.f);
            if (diag) {
                if (c     > q0) f0 = -6.0e4f;
                if (c + 1 > q0) f1 = -6.0e4f;
                if (c     > q1) f2 = -6.0e4f;
                if (c + 1 > q1) f3 = -6.0e4f;
            }
            ph[nn][0] = ex2_h2(pack_h2(f0, f1));
            ph[nn][1] = ex2_h2(pack_h2(f2, f3));
        }

        // ---- l accumulate via ones-MMA (persistent C-fragment) ----
#pragma unroll
        for (int ks = 0; ks < 4; ks++)
            mma_f16(cL, ph[2 * ks][0], ph[2 * ks][1], ph[2 * ks + 1][0], ph[2 * ks + 1][1],
                    ones_b, ones_b);
    }
    // drain: PV of the final tile
    pv_block(nkt - 1);

    // l lives in cL[0]/cL[2] on tid4==0 lanes; broadcast within quad
    float l0 = __shfl_sync(0xffffffffu, cL[0], lane & ~3);
    float l1 = __shfl_sync(0xffffffffu, cL[2], lane & ~3);
    float inv0 = 1.f / l0;
    float inv1 = 1.f / l1;
#pragma unroll
    for (int nn = 0; nn < 8; nn++) {
        int d = nn * 8 + tid4 * 2;
        float* o0p = out + ((size_t)(b * TT + q0)) * (NH * HD) + h * HD + d;
        *(float2*)o0p = make_float2(cO[nn][0] * inv0, cO[nn][1] * inv0);
        float* o1p = out + ((size_t)(b * TT + q1)) * (NH * HD) + h * HD + d;
        *(float2*)o1p = make_float2(cO[nn][2] * inv1, cO[nn][3] * inv1);
    }
}

// ---------------------------------------------------------------------------
extern "C" void kernel_launch(void* const* d_in, const int* in_sizes, int n_in,
                              void* d_out, int out_size) {
    const float* X    = (const float*)d_in[0];
    const float* mask = (const float*)d_in[1];
    const float* Wq = (const float*)d_in[2];
    const float* bq = (const float*)d_in[3];
    const float* Aq = (const float*)d_in[4];
    const float* Bq = (const float*)d_in[5];
    const float* Wk = (const float*)d_in[6];
    const float* bk = (const float*)d_in[7];
    const float* Ak = (const float*)d_in[8];
    const float* Bk = (const float*)d_in[9];
    const float* Wv = (const float*)d_in[10];
    const float* bv = (const float*)d_in[11];
    const float* Av = (const float*)d_in[12];
    const float* Bv = (const float*)d_in[13];
    float* out = (float*)d_out;

    // 1) fold LoRA (vectorized) + convert X (single launch)
    prep_kernel<<<PREP_BLOCKS, 256>>>(X, Wq, Aq, Bq, Wk, Ak, Bk, Wv, Av, Bv);

    // 2) fused QKV projection (fp16 mma, BK=64, smem-staged coalesced epilogue)
    cudaFuncSetAttribute(qkv_gemm_mma, cudaFuncAttributeMaxDynamicSharedMemorySize, GEMM_SMEM);
    qkv_gemm_mma<<<dim3(3 * HID / 128, BB * TT / 128), 256, GEMM_SMEM>>>(bq, bk, bv);

    // 3) causal flash attention (R15 — max-free softmax, PV pipelined)
    cudaFuncSetAttribute(attn_mma, cudaFuncAttributeMaxDynamicSharedMemorySize, ATTN_SMEM);
    attn_mma<<<dim3(TT / QR, NH, BB), 256, ATTN_SMEM>>>(mask, out);
    (void)in_sizes; (void)n_in; (void)out_size;
}